// round 4
// baseline (speedup 1.0000x reference)
#include <cuda_runtime.h>

#define BB   2048
#define CC   128
#define II   16
#define EE   10
#define NT   816     // symmetric triples i<=j<=l
#define NP   136     // symmetric pairs  i<=j
#define NS   16      // singles
#define NTOT 968     // NT+NP+NS
#define K30  23
#define K31  33
#define K20  4
#define K21  5

// ---------------- device scratch (no allocations allowed) ----------------
__device__ float g_U3sym0[NT * K30];
__device__ float g_U3sym1[3 * NT * K31];
__device__ float g_U2sym0[NP * K20];
__device__ float g_U2sym1[3 * NP * K21];
__device__ float g_S[(size_t)EE * CC * NTOT * 4];   // [e][c][t][m]  ~19.8MB
__device__ int   g_elem[BB];
__device__ int   g_order[BB];
__device__ int   g_counts[EE];
__device__ int   g_offsets[EE + 1];
__device__ int   g_cursors[EE];

// ---------------- index helpers ----------------
__device__ __forceinline__ void unrank3(int t, int& a, int& b, int& c) {
    int n = 0;
    for (int i = 0; i < II; i++)
        for (int j = i; j < II; j++) {
            int len = II - j;
            if (t < n + len) { a = i; b = j; c = j + (t - n); return; }
            n += len;
        }
    a = b = c = 0;
}
__device__ __forceinline__ void unrank2(int t, int& a, int& b) {
    int n = 0;
    for (int i = 0; i < II; i++)
        for (int j = i; j < II; j++) {
            if (t == n) { a = i; b = j; return; }
            n++;
        }
    a = b = 0;
}

// ---------------- symmetrize U3 over distinct permutations ----------------
__global__ void k_sym3(const float* __restrict__ U3_0, const float* __restrict__ U3_1) {
    int t  = blockIdx.x;       // 0..815
    int ms = blockIdx.y;       // m-slot 0..3
    int k  = threadIdx.x;
    int K  = (ms == 0) ? K30 : K31;
    if (k >= K) return;
    int a, b, c;
    unrank3(t, a, b, c);
    int P[6][3] = {{a,b,c},{a,c,b},{b,a,c},{b,c,a},{c,a,b},{c,b,a}};
    float s = 0.f;
    for (int p = 0; p < 6; p++) {
        bool dup = false;
        for (int q = 0; q < p; q++)
            if (P[q][0]==P[p][0] && P[q][1]==P[p][1] && P[q][2]==P[p][2]) { dup = true; break; }
        if (dup) continue;
        int i = P[p][0], j = P[p][1], l = P[p][2];
        if (ms == 0) s += U3_0[((i*II + j)*II + l)*K30 + k];
        else         s += U3_1[((((ms-1)*II + i)*II + j)*II + l)*K31 + k];
    }
    if (ms == 0) g_U3sym0[t*K30 + k] = s;
    else         g_U3sym1[((ms-1)*NT + t)*K31 + k] = s;
}

__global__ void k_sym2(const float* __restrict__ U2_0, const float* __restrict__ U2_1) {
    int p  = blockIdx.x;       // 0..135
    int ms = blockIdx.y;
    int k  = threadIdx.x;
    int K  = (ms == 0) ? K20 : K21;
    if (k >= K) return;
    int a, b;
    unrank2(p, a, b);
    float s;
    if (ms == 0) {
        s = U2_0[(a*II + b)*K20 + k];
        if (a != b) s += U2_0[(b*II + a)*K20 + k];
        g_U2sym0[p*K20 + k] = s;
    } else {
        int mm = ms - 1;
        s = U2_1[((mm*II + a)*II + b)*K21 + k];
        if (a != b) s += U2_1[((mm*II + b)*II + a)*K21 + k];
        g_U2sym1[(mm*NP + p)*K21 + k] = s;
    }
}

// ---------------- element bucketing ----------------
__global__ void k_zero() {
    int t = threadIdx.x;
    if (t < EE) { g_counts[t] = 0; g_cursors[t] = 0; }
}
__global__ void k_elem(const float* __restrict__ y) {
    int b = blockIdx.x * blockDim.x + threadIdx.x;
    if (b >= BB) return;
    int e = 0; float best = y[b*EE];
    for (int q = 1; q < EE; q++) { float v = y[b*EE + q]; if (v > best) { best = v; e = q; } }
    g_elem[b] = e;
    atomicAdd(&g_counts[e], 1);
}
__global__ void k_off() {
    if (threadIdx.x == 0 && blockIdx.x == 0) {
        int s = 0;
        for (int e = 0; e < EE; e++) { g_offsets[e] = s; s += g_counts[e]; }
        g_offsets[EE] = s;
    }
}
__global__ void k_scatter() {
    int b = blockIdx.x * blockDim.x + threadIdx.x;
    if (b >= BB) return;
    int e = g_elem[b];
    int pos = atomicAdd(&g_cursors[e], 1);
    g_order[g_offsets[e] + pos] = b;
}

// ---------------- build S[e][c][t][m] ----------------
__global__ void k_S(const float* __restrict__ W3_0, const float* __restrict__ W2_0,
                    const float* __restrict__ W1_0, const float* __restrict__ W3_1,
                    const float* __restrict__ W2_1, const float* __restrict__ W1_1,
                    const float* __restrict__ U1_0, const float* __restrict__ U1_1) {
    int c = blockIdx.x;    // 0..127
    int e = blockIdx.y;    // 0..9
    for (int t = threadIdx.x; t < NTOT; t += blockDim.x) {
        float r[4];
        if (t < NT) {
            // cubic slot
            {
                const float* U = &g_U3sym0[t*K30];
                const float* W = W3_0 + (size_t)e*K30*CC + c;
                float s = 0.f;
                for (int k = 0; k < K30; k++) s += U[k] * W[k*CC];
                r[0] = s;
            }
            for (int m = 1; m < 4; m++) {
                const float* U = &g_U3sym1[((m-1)*NT + t)*K31];
                const float* W = W3_1 + (size_t)e*K31*CC + c;
                float s = 0.f;
                for (int k = 0; k < K31; k++) s += U[k] * W[k*CC];
                r[m] = s;
            }
        } else if (t < NT + NP) {
            int p = t - NT;
            {
                const float* U = &g_U2sym0[p*K20];
                const float* W = W2_0 + (size_t)e*K20*CC + c;
                float s = 0.f;
                for (int k = 0; k < K20; k++) s += U[k] * W[k*CC];
                r[0] = s;
            }
            for (int m = 1; m < 4; m++) {
                const float* U = &g_U2sym1[((m-1)*NP + p)*K21];
                const float* W = W2_1 + (size_t)e*K21*CC + c;
                float s = 0.f;
                for (int k = 0; k < K21; k++) s += U[k] * W[k*CC];
                r[m] = s;
            }
        } else {
            int i = t - NT - NP;
            r[0] = U1_0[i] * W1_0[(size_t)e*CC + c];                 // (1,16,1)
            for (int m = 1; m < 4; m++)
                r[m] = U1_1[(m-1)*II + i] * W1_1[(size_t)e*CC + c];  // (3,16,1)
        }
        float4* dst = reinterpret_cast<float4*>(&g_S[(((size_t)e*CC + c)*NTOT + t)*4]);
        *dst = make_float4(r[0], r[1], r[2], r[3]);
    }
}

// ---------------- main contraction: one block per (e,c), one node per lane ----------------
__global__ void __launch_bounds__(256) k_main(const float* __restrict__ x,
                                              float* __restrict__ out) {
    __shared__ float Ss[NTOT * 4];
    __shared__ float xs[II][256];
    int c = blockIdx.x;
    int e = blockIdx.y;

    const float4* Sg  = reinterpret_cast<const float4*>(&g_S[((size_t)e*CC + c)*NTOT*4]);
    float4*       Ss4 = reinterpret_cast<float4*>(Ss);
    for (int t = threadIdx.x; t < NTOT; t += 256) Ss4[t] = Sg[t];

    int off = g_offsets[e];
    int n   = g_offsets[e+1] - off;

    for (int base = 0; base < n; base += 256) {
        int slot = base + threadIdx.x;
        int nd = (slot < n) ? g_order[off + slot] : -1;
        {
            const float4* xp = (nd >= 0)
                ? reinterpret_cast<const float4*>(x + ((size_t)nd*CC + c)*II) : nullptr;
            #pragma unroll
            for (int q = 0; q < 4; q++) {
                float4 v = (nd >= 0) ? xp[q] : make_float4(0.f, 0.f, 0.f, 0.f);
                xs[q*4 + 0][threadIdx.x] = v.x;
                xs[q*4 + 1][threadIdx.x] = v.y;
                xs[q*4 + 2][threadIdx.x] = v.z;
                xs[q*4 + 3][threadIdx.x] = v.w;
            }
        }
        __syncthreads();

        float a0 = 0.f, a1 = 0.f, a2 = 0.f, a3 = 0.f;
        const int lane = threadIdx.x;
        const float4* S4 = reinterpret_cast<const float4*>(Ss);
        int t = 0;

        // cubic: sum_{i<=j<=l} x_i x_j x_l * S3[t][m]
        #pragma unroll
        for (int i = 0; i < II; i++) {
            float xi = xs[i][lane];
            #pragma unroll
            for (int j = i; j < II; j++) {
                float pij = xi * xs[j][lane];
                #pragma unroll
                for (int l = j; l < II; l++) {
                    float mono = pij * xs[l][lane];
                    float4 s = S4[t++];
                    a0 = fmaf(mono, s.x, a0);
                    a1 = fmaf(mono, s.y, a1);
                    a2 = fmaf(mono, s.z, a2);
                    a3 = fmaf(mono, s.w, a3);
                }
            }
        }
        // quadratic: sum_{i<=j} x_i x_j * S2[t][m]
        #pragma unroll
        for (int i = 0; i < II; i++) {
            float xi = xs[i][lane];
            #pragma unroll
            for (int j = i; j < II; j++) {
                float mono = xi * xs[j][lane];
                float4 s = S4[t++];
                a0 = fmaf(mono, s.x, a0);
                a1 = fmaf(mono, s.y, a1);
                a2 = fmaf(mono, s.z, a2);
                a3 = fmaf(mono, s.w, a3);
            }
        }
        // linear: sum_i x_i * S1[t][m]
        #pragma unroll
        for (int i = 0; i < II; i++) {
            float mono = xs[i][lane];
            float4 s = S4[t++];
            a0 = fmaf(mono, s.x, a0);
            a1 = fmaf(mono, s.y, a1);
            a2 = fmaf(mono, s.z, a2);
            a3 = fmaf(mono, s.w, a3);
        }

        if (nd >= 0) {
            float* o = out + (size_t)nd * (4*CC);
            o[c]              = a0;          // 0e output  -> cols [0,128)
            o[CC + c*3 + 0]   = a1;          // 1o output  -> cols [128,512), m fastest
            o[CC + c*3 + 1]   = a2;
            o[CC + c*3 + 2]   = a3;
        }
        __syncthreads();
    }
}

// ---------------- launch ----------------
extern "C" void kernel_launch(void* const* d_in, const int* in_sizes, int n_in,
                              void* d_out, int out_size) {
    const float* x    = (const float*)d_in[0];
    const float* y    = (const float*)d_in[1];
    const float* U3_0 = (const float*)d_in[2];
    const float* U2_0 = (const float*)d_in[3];
    const float* U1_0 = (const float*)d_in[4];
    const float* W3_0 = (const float*)d_in[5];
    const float* W2_0 = (const float*)d_in[6];
    const float* W1_0 = (const float*)d_in[7];
    const float* U3_1 = (const float*)d_in[8];
    const float* U2_1 = (const float*)d_in[9];
    const float* U1_1 = (const float*)d_in[10];
    const float* W3_1 = (const float*)d_in[11];
    const float* W2_1 = (const float*)d_in[12];
    const float* W1_1 = (const float*)d_in[13];
    float* out = (float*)d_out;

    k_sym3<<<dim3(NT, 4), 64>>>(U3_0, U3_1);
    k_sym2<<<dim3(NP, 4), 32>>>(U2_0, U2_1);
    k_zero<<<1, 32>>>();
    k_elem<<<(BB + 255) / 256, 256>>>(y);
    k_off<<<1, 32>>>();
    k_scatter<<<(BB + 255) / 256, 256>>>();
    k_S<<<dim3(CC, EE), 256>>>(W3_0, W2_0, W1_0, W3_1, W2_1, W1_1, U1_0, U1_1);
    k_main<<<dim3(CC, EE), 256>>>(x, out);
}

// round 5
// speedup vs baseline: 1.3701x; 1.3701x over previous
#include <cuda_runtime.h>

#define BB   2048
#define CC   128
#define II   16
#define EE   10
#define NT   816     // symmetric triples i<=j<=l
#define NP   136     // symmetric pairs  i<=j
#define NS   16      // singles
#define NTOT 968     // NT+NP+NS
#define K30  23
#define K31  33
#define K20  4
#define K21  5

// ---------------- device scratch (no allocations allowed) ----------------
__device__ float g_U3sym0[NT * K30];
__device__ float g_U3sym1[3 * NT * K31];
__device__ float g_U2sym0[NP * K20];
__device__ float g_U2sym1[3 * NP * K21];
// S planes: [e][c][m][t]  (plane-major so k_S writes are coalesced over t)
__device__ float g_S[(size_t)EE * CC * 4 * NTOT];   // ~19.8MB
__device__ int   g_elem[BB];
__device__ int   g_order[BB];
__device__ int   g_counts[EE];
__device__ int   g_offsets[EE + 1];
__device__ int   g_cursors[EE];

// ---------------- f32x2 packed helpers ----------------
__device__ __forceinline__ unsigned long long pk2(float a, float b) {
    unsigned long long r;
    asm("mov.b64 %0, {%1, %2};" : "=l"(r) : "f"(a), "f"(b));
    return r;
}
__device__ __forceinline__ unsigned long long dup2(float a) {
    unsigned long long r;
    asm("mov.b64 %0, {%1, %1};" : "=l"(r) : "f"(a));
    return r;
}
__device__ __forceinline__ void unpk2(unsigned long long v, float& lo, float& hi) {
    asm("mov.b64 {%0, %1}, %2;" : "=f"(lo), "=f"(hi) : "l"(v));
}
#define MUL2(d, a, b) asm("mul.rn.f32x2 %0, %1, %2;" : "=l"(d) : "l"(a), "l"(b))
#define FMA2(d, a, b) asm("fma.rn.f32x2 %0, %1, %2, %0;" : "+l"(d) : "l"(a), "l"(b))

// ---------------- index helpers ----------------
__device__ __forceinline__ void unrank3(int t, int& a, int& b, int& c) {
    int n = 0;
    for (int i = 0; i < II; i++)
        for (int j = i; j < II; j++) {
            int len = II - j;
            if (t < n + len) { a = i; b = j; c = j + (t - n); return; }
            n += len;
        }
    a = b = c = 0;
}
__device__ __forceinline__ void unrank2(int t, int& a, int& b) {
    int n = 0;
    for (int i = 0; i < II; i++)
        for (int j = i; j < II; j++) {
            if (t == n) { a = i; b = j; return; }
            n++;
        }
    a = b = 0;
}

// ---------------- symmetrize U3 over distinct permutations ----------------
__global__ void k_sym3(const float* __restrict__ U3_0, const float* __restrict__ U3_1) {
    int t  = blockIdx.x;       // 0..815
    int ms = blockIdx.y;       // m-slot 0..3
    int k  = threadIdx.x;
    int K  = (ms == 0) ? K30 : K31;
    if (k >= K) return;
    int a, b, c;
    unrank3(t, a, b, c);
    int P[6][3] = {{a,b,c},{a,c,b},{b,a,c},{b,c,a},{c,a,b},{c,b,a}};
    float s = 0.f;
    for (int p = 0; p < 6; p++) {
        bool dup = false;
        for (int q = 0; q < p; q++)
            if (P[q][0]==P[p][0] && P[q][1]==P[p][1] && P[q][2]==P[p][2]) { dup = true; break; }
        if (dup) continue;
        int i = P[p][0], j = P[p][1], l = P[p][2];
        if (ms == 0) s += U3_0[((i*II + j)*II + l)*K30 + k];
        else         s += U3_1[((((ms-1)*II + i)*II + j)*II + l)*K31 + k];
    }
    if (ms == 0) g_U3sym0[t*K30 + k] = s;
    else         g_U3sym1[((ms-1)*NT + t)*K31 + k] = s;
}

__global__ void k_sym2(const float* __restrict__ U2_0, const float* __restrict__ U2_1) {
    int p  = blockIdx.x;       // 0..135
    int ms = blockIdx.y;
    int k  = threadIdx.x;
    int K  = (ms == 0) ? K20 : K21;
    if (k >= K) return;
    int a, b;
    unrank2(p, a, b);
    float s;
    if (ms == 0) {
        s = U2_0[(a*II + b)*K20 + k];
        if (a != b) s += U2_0[(b*II + a)*K20 + k];
        g_U2sym0[p*K20 + k] = s;
    } else {
        int mm = ms - 1;
        s = U2_1[((mm*II + a)*II + b)*K21 + k];
        if (a != b) s += U2_1[((mm*II + b)*II + a)*K21 + k];
        g_U2sym1[(mm*NP + p)*K21 + k] = s;
    }
}

// ---------------- element bucketing ----------------
__global__ void k_zero() {
    int t = threadIdx.x;
    if (t < EE) { g_counts[t] = 0; g_cursors[t] = 0; }
}
__global__ void k_elem(const float* __restrict__ y) {
    int b = blockIdx.x * blockDim.x + threadIdx.x;
    if (b >= BB) return;
    int e = 0; float best = y[b*EE];
    for (int q = 1; q < EE; q++) { float v = y[b*EE + q]; if (v > best) { best = v; e = q; } }
    g_elem[b] = e;
    atomicAdd(&g_counts[e], 1);
}
__global__ void k_off() {
    if (threadIdx.x == 0 && blockIdx.x == 0) {
        int s = 0;
        for (int e = 0; e < EE; e++) { g_offsets[e] = s; s += g_counts[e]; }
        g_offsets[EE] = s;
    }
}
__global__ void k_scatter() {
    int b = blockIdx.x * blockDim.x + threadIdx.x;
    if (b >= BB) return;
    int e = g_elem[b];
    int pos = atomicAdd(&g_cursors[e], 1);
    g_order[g_offsets[e] + pos] = b;
}

// ---------------- build S planes: grid (cchunk=4, tchunk=4, e=10) ----------------
// Per block: 32 c-values, 256 t-slots. W slices in smem, U coeffs in registers
// (per-m passes), writes coalesced over t.
__global__ void __launch_bounds__(256) k_S(
        const float* __restrict__ W3_0, const float* __restrict__ W2_0,
        const float* __restrict__ W1_0, const float* __restrict__ W3_1,
        const float* __restrict__ W2_1, const float* __restrict__ W1_1,
        const float* __restrict__ U1_0, const float* __restrict__ U1_1) {
    __shared__ float Ws30[K30][32];
    __shared__ float Ws31[K31][32];
    __shared__ float Ws20[K20][32];
    __shared__ float Ws21[K21][32];
    __shared__ float Ws10[32];
    __shared__ float Ws11[32];

    int tid = threadIdx.x;
    int c0  = blockIdx.x * 32;
    int e   = blockIdx.z;
    int t   = blockIdx.y * 256 + tid;

    for (int idx = tid; idx < K30*32; idx += 256)
        Ws30[idx/32][idx%32] = W3_0[((size_t)e*K30 + idx/32)*CC + c0 + idx%32];
    for (int idx = tid; idx < K31*32; idx += 256)
        Ws31[idx/32][idx%32] = W3_1[((size_t)e*K31 + idx/32)*CC + c0 + idx%32];
    for (int idx = tid; idx < K20*32; idx += 256)
        Ws20[idx/32][idx%32] = W2_0[((size_t)e*K20 + idx/32)*CC + c0 + idx%32];
    for (int idx = tid; idx < K21*32; idx += 256)
        Ws21[idx/32][idx%32] = W2_1[((size_t)e*K21 + idx/32)*CC + c0 + idx%32];
    if (tid < 32) {
        Ws10[tid] = W1_0[(size_t)e*CC + c0 + tid];
        Ws11[tid] = W1_1[(size_t)e*CC + c0 + tid];
    }
    __syncthreads();
    if (t >= NTOT) return;

    float* plane = g_S + ((size_t)e*CC + c0) * 4 * NTOT;   // then + (c*4+m)*NTOT + t

    if (t < NT) {
        // cubic slots
        {   // m = 0
            float u[K30];
            #pragma unroll
            for (int k = 0; k < K30; k++) u[k] = g_U3sym0[t*K30 + k];
            for (int c = 0; c < 32; c++) {
                float s = 0.f;
                #pragma unroll
                for (int k = 0; k < K30; k++) s = fmaf(u[k], Ws30[k][c], s);
                plane[(size_t)(c*4 + 0)*NTOT + t] = s;
            }
        }
        for (int m = 1; m < 4; m++) {
            float u[K31];
            #pragma unroll
            for (int k = 0; k < K31; k++) u[k] = g_U3sym1[((m-1)*NT + t)*K31 + k];
            for (int c = 0; c < 32; c++) {
                float s = 0.f;
                #pragma unroll
                for (int k = 0; k < K31; k++) s = fmaf(u[k], Ws31[k][c], s);
                plane[(size_t)(c*4 + m)*NTOT + t] = s;
            }
        }
    } else if (t < NT + NP) {
        int p = t - NT;
        {   float u[K20];
            #pragma unroll
            for (int k = 0; k < K20; k++) u[k] = g_U2sym0[p*K20 + k];
            for (int c = 0; c < 32; c++) {
                float s = 0.f;
                #pragma unroll
                for (int k = 0; k < K20; k++) s = fmaf(u[k], Ws20[k][c], s);
                plane[(size_t)(c*4 + 0)*NTOT + t] = s;
            }
        }
        for (int m = 1; m < 4; m++) {
            float u[K21];
            #pragma unroll
            for (int k = 0; k < K21; k++) u[k] = g_U2sym1[((m-1)*NP + p)*K21 + k];
            for (int c = 0; c < 32; c++) {
                float s = 0.f;
                #pragma unroll
                for (int k = 0; k < K21; k++) s = fmaf(u[k], Ws21[k][c], s);
                plane[(size_t)(c*4 + m)*NTOT + t] = s;
            }
        }
    } else {
        int i = t - NT - NP;
        float u0 = U1_0[i];
        float u1 = U1_1[0*II + i], u2 = U1_1[1*II + i], u3 = U1_1[2*II + i];
        for (int c = 0; c < 32; c++) {
            plane[(size_t)(c*4 + 0)*NTOT + t] = u0 * Ws10[c];
            plane[(size_t)(c*4 + 1)*NTOT + t] = u1 * Ws11[c];
            plane[(size_t)(c*4 + 2)*NTOT + t] = u2 * Ws11[c];
            plane[(size_t)(c*4 + 3)*NTOT + t] = u3 * Ws11[c];
        }
    }
}

// ---------------- main contraction: one block per (c,e), 2 nodes per lane (f32x2) ----------------
__global__ void __launch_bounds__(128) k_main(const float* __restrict__ x,
                                              float* __restrict__ out) {
    __shared__ unsigned long long Sd[NTOT * 4];   // [t][m] duplicated pairs, 31KB
    int c = blockIdx.x;
    int e = blockIdx.y;
    int tid = threadIdx.x;

    // Build duplicated S in smem from the 4 planes
    const float* P = g_S + ((size_t)e*CC + c) * 4 * NTOT;
    for (int t = tid; t < NTOT; t += 128) {
        Sd[t*4 + 0] = dup2(P[0*NTOT + t]);
        Sd[t*4 + 1] = dup2(P[1*NTOT + t]);
        Sd[t*4 + 2] = dup2(P[2*NTOT + t]);
        Sd[t*4 + 3] = dup2(P[3*NTOT + t]);
    }
    __syncthreads();

    const ulonglong2* S2 = reinterpret_cast<const ulonglong2*>(Sd);
    int off = g_offsets[e];
    int n   = g_offsets[e+1] - off;

    for (int base = 0; base < n; base += 256) {
        int iA = base + 2*tid;
        int iB = iA + 1;
        int ndA = (iA < n) ? g_order[off + iA] : -1;
        int ndB = (iB < n) ? g_order[off + iB] : -1;

        // per-lane packed x values: xv[i] = (xA_i, xB_i)
        unsigned long long xv[II];
        {
            float fa[II], fb[II];
            const float4* pa = (ndA >= 0)
                ? reinterpret_cast<const float4*>(x + ((size_t)ndA*CC + c)*II) : nullptr;
            const float4* pb = (ndB >= 0)
                ? reinterpret_cast<const float4*>(x + ((size_t)ndB*CC + c)*II) : nullptr;
            #pragma unroll
            for (int q = 0; q < 4; q++) {
                float4 va = (ndA >= 0) ? pa[q] : make_float4(0.f,0.f,0.f,0.f);
                float4 vb = (ndB >= 0) ? pb[q] : make_float4(0.f,0.f,0.f,0.f);
                fa[q*4+0]=va.x; fa[q*4+1]=va.y; fa[q*4+2]=va.z; fa[q*4+3]=va.w;
                fb[q*4+0]=vb.x; fb[q*4+1]=vb.y; fb[q*4+2]=vb.z; fb[q*4+3]=vb.w;
            }
            #pragma unroll
            for (int i = 0; i < II; i++) xv[i] = pk2(fa[i], fb[i]);
        }

        unsigned long long a0 = 0ull, a1 = 0ull, a2 = 0ull, a3 = 0ull;
        int t = 0;   // cubic slot counter (compile-time after unroll)
        int tq = NT; // quadratic slot counter
        #pragma unroll
        for (int i = 0; i < II; i++) {
            #pragma unroll
            for (int j = i; j < II; j++) {
                unsigned long long pij;
                MUL2(pij, xv[i], xv[j]);
                #pragma unroll
                for (int l = j; l < II; l++) {
                    unsigned long long mono;
                    MUL2(mono, pij, xv[l]);
                    ulonglong2 sA = S2[2*t];
                    ulonglong2 sB = S2[2*t + 1];
                    FMA2(a0, mono, sA.x);
                    FMA2(a1, mono, sA.y);
                    FMA2(a2, mono, sB.x);
                    FMA2(a3, mono, sB.y);
                    t++;
                }
                // quadratic slot (i,j): monomial is exactly pij
                {
                    ulonglong2 qA = S2[2*tq];
                    ulonglong2 qB = S2[2*tq + 1];
                    FMA2(a0, pij, qA.x);
                    FMA2(a1, pij, qA.y);
                    FMA2(a2, pij, qB.x);
                    FMA2(a3, pij, qB.y);
                    tq++;
                }
            }
            // linear slot i: monomial is xv[i]
            {
                int ts = NT + NP + i;
                ulonglong2 lA = S2[2*ts];
                ulonglong2 lB = S2[2*ts + 1];
                FMA2(a0, xv[i], lA.x);
                FMA2(a1, xv[i], lA.y);
                FMA2(a2, xv[i], lB.x);
                FMA2(a3, xv[i], lB.y);
            }
        }

        float a0A,a0B,a1A,a1B,a2A,a2B,a3A,a3B;
        unpk2(a0, a0A, a0B);
        unpk2(a1, a1A, a1B);
        unpk2(a2, a2A, a2B);
        unpk2(a3, a3A, a3B);

        if (ndA >= 0) {
            float* o = out + (size_t)ndA * (4*CC);
            o[c]            = a0A;
            o[CC + c*3 + 0] = a1A;
            o[CC + c*3 + 1] = a2A;
            o[CC + c*3 + 2] = a3A;
        }
        if (ndB >= 0) {
            float* o = out + (size_t)ndB * (4*CC);
            o[c]            = a0B;
            o[CC + c*3 + 0] = a1B;
            o[CC + c*3 + 1] = a2B;
            o[CC + c*3 + 2] = a3B;
        }
    }
}

// ---------------- launch ----------------
extern "C" void kernel_launch(void* const* d_in, const int* in_sizes, int n_in,
                              void* d_out, int out_size) {
    const float* x    = (const float*)d_in[0];
    const float* y    = (const float*)d_in[1];
    const float* U3_0 = (const float*)d_in[2];
    const float* U2_0 = (const float*)d_in[3];
    const float* U1_0 = (const float*)d_in[4];
    const float* W3_0 = (const float*)d_in[5];
    const float* W2_0 = (const float*)d_in[6];
    const float* W1_0 = (const float*)d_in[7];
    const float* U3_1 = (const float*)d_in[8];
    const float* U2_1 = (const float*)d_in[9];
    const float* U1_1 = (const float*)d_in[10];
    const float* W3_1 = (const float*)d_in[11];
    const float* W2_1 = (const float*)d_in[12];
    const float* W1_1 = (const float*)d_in[13];
    float* out = (float*)d_out;

    k_sym3<<<dim3(NT, 4), 64>>>(U3_0, U3_1);
    k_sym2<<<dim3(NP, 4), 32>>>(U2_0, U2_1);
    k_zero<<<1, 32>>>();
    k_elem<<<(BB + 255) / 256, 256>>>(y);
    k_off<<<1, 32>>>();
    k_scatter<<<(BB + 255) / 256, 256>>>();
    k_S<<<dim3(4, 4, EE), 256>>>(W3_0, W2_0, W1_0, W3_1, W2_1, W1_1, U1_0, U1_1);
    k_main<<<dim3(CC, EE), 128>>>(x, out);
}